// round 4
// baseline (speedup 1.0000x reference)
#include <cuda_runtime.h>
#include <cstddef>

// Problem constants
constexpr int B      = 2;
constexpr int H      = 64;
constexpr int W      = 64;
constexpr int C      = 128;
constexpr int PW     = W / 2;             // 32
constexpr int NPOOL  = (H/2) * (W/2) * C; // 131072
constexpr int NOUT   = 32;
constexpr long long NIN = (long long)H * W * C;        // 524288
constexpr long long WZ  = (long long)B * NIN * NOUT;   // 33554432 elems per w_zero tensor

// Output layout (flattened tuple):
//   [0, WZ)             : w_zero (upper)
//   [WZ, WZ+64)         : b_out_u_ (B,1,32)
//   [WZ+64, 2WZ+64)     : w_zero (lower)
//   [2WZ+64, 2WZ+128)   : b_out_l_ (B,1,32)
constexpr long long OFF_BU = WZ;
constexpr long long OFF_W2 = WZ + 64;
constexpr long long OFF_BL = 2 * WZ + 64;

constexpr int TILE_P  = 1024;
constexpr int NCHUNK  = NPOOL / TILE_P;   // 128
constexpr int NRED    = B * NCHUNK;       // 256 reduce blocks
constexpr int NZB     = 2048;             // zero-fill blocks (1024 per region); NB: "NZERO" is a POSIX macro!
constexpr int NBLOCKS = NRED + NZB;
constexpr int THREADS = 256;
constexpr int NWARP   = THREADS / 32;     // 8

// float4s per zero block: WZ floats per region / 4 / 1024 blocks
constexpr int ZV_PER_BLOCK  = (int)(WZ / 4 / (NZB / 2));    // 8192
constexpr int ZV_PER_THREAD = ZV_PER_BLOCK / THREADS;       // 32

__device__ float g_scratch_u[NRED * NOUT];
__device__ float g_scratch_l[NRED * NOUT];
__device__ unsigned int g_done = 0;

__device__ __forceinline__ void stg_cs_zero16(float4* p) {
    asm volatile("st.global.cs.v4.f32 [%0], {%1,%1,%1,%1};"
                 :: "l"(p), "f"(0.0f) : "memory");
}

__global__ __launch_bounds__(THREADS)
void fused_kernel(const float* __restrict__ uc,
                  const float* __restrict__ lc,
                  const float* __restrict__ wu,
                  const float* __restrict__ wl,
                  const float* __restrict__ bu_bias,
                  const float* __restrict__ bl_bias,
                  float* __restrict__ out)
{
    const int t   = threadIdx.x;
    const int blk = blockIdx.x;

    if (blk < NRED) {
        // ---------------- reduce block ----------------
        __shared__ float s_bu[TILE_P];
        __shared__ float s_bl[TILE_P];
        __shared__ float r_u[NWARP][NOUT];
        __shared__ float r_l[NWARP][NOUT];

        const int chunk = blk & (NCHUNK - 1);
        const int b     = blk >> 7;           // NCHUNK == 128
        const int p0    = chunk * TILE_P;

        const float* ucb = uc + (size_t)b * H * W * C;
        const float* lcb = lc + (size_t)b * H * W * C;
        #pragma unroll
        for (int i = t; i < TILE_P; i += THREADS) {
            const int p  = p0 + i;
            const int c  = p & (C - 1);
            const int pw = (p >> 7) & (PW - 1);
            const int ph = p >> 12;
            const int base = ((2 * ph) * W + 2 * pw) * C + c;
            float u0 = ucb[base];
            float u1 = ucb[base + C];
            float u2 = ucb[base + W * C];
            float u3 = ucb[base + W * C + C];
            float l0 = lcb[base];
            float l1 = lcb[base + C];
            float l2 = lcb[base + W * C];
            float l3 = lcb[base + W * C + C];
            s_bu[i] = fmaxf(fmaxf(u0, u1), fmaxf(u2, u3));
            s_bl[i] = fmaxf(fmaxf(l0, l1), fmaxf(l2, l3));
        }
        __syncthreads();

        const int warp = t >> 5;
        const int lane = t & 31;
        float au = 0.0f, al = 0.0f;
        const float* wub = wu + ((size_t)b * NPOOL + p0) * NOUT + lane;
        const float* wlb = wl + ((size_t)b * NPOOL + p0) * NOUT + lane;

        #pragma unroll 4
        for (int i = warp; i < TILE_P; i += NWARP) {
            const float vu = wub[(size_t)i * NOUT];
            const float vl = wlb[(size_t)i * NOUT];
            const float pu = s_bu[i];
            const float pl = s_bl[i];
            au += fmaxf(vu, 0.0f) * pu + fminf(vu, 0.0f) * pl;
            al += fmaxf(vl, 0.0f) * pl + fminf(vl, 0.0f) * pu;
        }

        r_u[warp][lane] = au;
        r_l[warp][lane] = al;
        __syncthreads();

        if (warp == 0) {
            float su = 0.0f, sl = 0.0f;
            #pragma unroll
            for (int k = 0; k < NWARP; k++) {
                su += r_u[k][lane];
                sl += r_l[k][lane];
            }
            g_scratch_u[blk * NOUT + lane] = su;
            g_scratch_l[blk * NOUT + lane] = sl;
        }
    } else {
        // ---------------- zero-fill block (streaming stores) ----------------
        const int z      = blk - NRED;
        const int region = z >> 10;                  // 0 or 1 (NZB/2 == 1024)
        const int zin    = z & 1023;
        float4* dst = reinterpret_cast<float4*>(
            out + (region == 0 ? 0LL : OFF_W2)) + (size_t)zin * ZV_PER_BLOCK;
        #pragma unroll
        for (int k = 0; k < ZV_PER_THREAD; k++)
            stg_cs_zero16(dst + (size_t)k * THREADS + t);
    }

    // ---------------- last-block finalize ----------------
    __shared__ bool s_last;
    __threadfence();
    __syncthreads();
    if (t == 0) {
        unsigned int prev = atomicAdd(&g_done, 1u);
        s_last = (prev == (unsigned int)(NBLOCKS - 1));
    }
    __syncthreads();
    if (!s_last) return;
    __threadfence();

    // 256 threads: t&127 selects (b, u/l, j); t>>7 selects chunk half
    {
        const int idx  = t & 127;
        const int half = t >> 7;
        const int b    = idx >> 6;          // 0..1
        const int ul   = (idx >> 5) & 1;    // 0 = upper, 1 = lower
        const int j    = idx & 31;
        const float* sc = ul ? g_scratch_l : g_scratch_u;
        float s = 0.0f;
        const int k0 = half * (NCHUNK / 2);
        #pragma unroll 8
        for (int k = 0; k < NCHUNK / 2; k++)
            s += sc[(b * NCHUNK + k0 + k) * NOUT + j];

        __shared__ float s_part[128];
        if (half == 1) s_part[idx] = s;
        __syncthreads();
        if (half == 0) {
            s += s_part[idx];
            const float bias = ul ? bl_bias[b * NOUT + j] : bu_bias[b * NOUT + j];
            const long long off = ul ? OFF_BL : OFF_BU;
            out[off + b * NOUT + j] = s + bias;
        }
        if (t == 0) g_done = 0;   // reset for next graph replay
    }
}

extern "C" void kernel_launch(void* const* d_in, const int* in_sizes, int n_in,
                              void* d_out, int out_size)
{
    // metadata order: y, x_0, u_c, l_c, w_out_u, b_out_u, w_out_l, b_out_l
    const float* uc = (const float*)d_in[2];
    const float* lc = (const float*)d_in[3];
    const float* wu = (const float*)d_in[4];
    const float* bu = (const float*)d_in[5];
    const float* wl = (const float*)d_in[6];
    const float* bl = (const float*)d_in[7];
    float* out = (float*)d_out;

    fused_kernel<<<NBLOCKS, THREADS>>>(uc, lc, wu, wl, bu, bl, out);
}